// round 8
// baseline (speedup 1.0000x reference)
#include <cuda_runtime.h>
#include <cuda_bf16.h>

#define BB   16
#define NN   128
#define HH   32
#define DD   5
#define NE1  1537     // NUM_EDGES + 1
#define NP1  129      // N + 1
#define RST  33       // odd stride -> conflict-free smem row access (phase 2)
#define SST  20       // sidx stride (ints): 4 consecutive pairs hit distinct banks

// Fused table in bf16: Tb[d][e][k] = bf16( sum_h E[e,h] * Wdis[d,h,k] )
// Row e=0 is exactly zero (edge_encoder_w[0] == 0).
__device__ __align__(16) __nv_bfloat16 g_Tb[DD * NE1 * HH];

// ---------------------------------------------------------------------------
__global__ void build_table_kernel(const float* __restrict__ E,     // (1537, 32)
                                   const float* __restrict__ Wdis)  // (>=5*32*32,)
{
    const int d  = blockIdx.y;
    const int k  = threadIdx.x;
    const int ey = threadIdx.y;
    const int e  = blockIdx.x * 8 + ey;

    __shared__ float Ws[HH * HH];
    __shared__ float Es[8][HH];

    const int t = ey * 32 + k;
    for (int i = t; i < HH * HH; i += 256)
        Ws[i] = Wdis[d * HH * HH + i];
    Es[ey][k] = (e < NE1) ? E[e * HH + k] : 0.f;
    __syncthreads();

    if (e < NE1) {
        float acc = 0.f;
#pragma unroll
        for (int h = 0; h < HH; ++h)
            acc += Es[ey][h] * Ws[h * HH + k];
        g_Tb[(d * NE1 + e) * HH + k] = __float2bfloat16_rn(acc);
    }
}

// packed bf16x2 add on uint2 (2x HADD2.BF16_V2)
#define U2_ADD(a, b) do { \
    asm("add.rn.bf16x2 %0, %0, %1;" : "+r"((a).x) : "r"((b).x)); \
    asm("add.rn.bf16x2 %0, %0, %1;" : "+r"((a).y) : "r"((b).y)); } while (0)

// ---------------------------------------------------------------------------
// Main: one block per (output row io, batch b). grid=(129, 16), block=256.
// ---------------------------------------------------------------------------
__global__ __launch_bounds__(256, 3)
void bias_kernel(const float* __restrict__ ab,        // (B, 129, 129)
                 const int*   __restrict__ spat,      // (B, 128, 128)
                 const int*   __restrict__ edge,      // (B, 128, 128, 5, 3)
                 const float* __restrict__ struct_w,  // (512, 32)
                 const float* __restrict__ virt,      // (1, 32)
                 float*       __restrict__ out)       // (B, 32, 129, 129)
{
    const int b    = blockIdx.y;
    const int io   = blockIdx.x;
    const int tid  = threadIdx.x;
    const int warp = tid >> 5;
    const int lane = tid & 31;

    __shared__ __align__(16) int   sidx[NN * SST];  // indices, 15 used of SST/pair
    __shared__ int   sspat[NN];
    __shared__ float row[NN * RST];                 // [pair][channel]
    __shared__ float ab_s[NP1];
    __shared__ float vs[HH];

    if (tid < HH)  vs[tid]   = virt[tid];
    if (tid < NP1) ab_s[tid] = ab[(b * NP1 + io) * NP1 + tid];

    if (io == 0) {
        __syncthreads();
#pragma unroll
        for (int hh = 0; hh < 4; ++hh) {
            const int h = warp + hh * 8;
            const float vh = vs[h];
            float* ob = out + (((size_t)b * HH + h) * NP1) * NP1;
#pragma unroll
            for (int k = 0; k < 5; ++k) {
                const int j = lane + 32 * k;
                if (j < NP1) ob[j] = fmaf(2.f, ab_s[j], vh);
            }
        }
        return;
    }

    const int ip    = io - 1;
    const int pbase = (b * NN + ip) * NN;

    // ---- stage indices (coalesced) into padded smem ----
    {
        const int* gsrc = edge + (size_t)pbase * 15;
#pragma unroll
        for (int it = 0; it < 8; ++it) {
            const int i = tid + it * 256;
            if (i < NN * 15)
                sidx[(i / 15) * SST + (i % 15)] = gsrc[i];
        }
        if (tid < NN) sspat[tid] = spat[pbase + tid];
    }
    __syncthreads();

    // ---- phase 1: 8 lanes per pair, 4 pairs per warp-iteration,
    //      software-pipelined index fetch + tree reduction ----
    const int g  = lane >> 3;          // pair group within warp (0..3)
    const int co = (lane & 7) * 4;     // this lane's 4 channels
    const __nv_bfloat16* Tco = g_Tb + co;
    const __nv_bfloat16* T0 = Tco;
    const __nv_bfloat16* T1 = Tco + 1 * NE1 * HH;
    const __nv_bfloat16* T2 = Tco + 2 * NE1 * HH;
    const __nv_bfloat16* T3 = Tco + 3 * NE1 * HH;
    const __nv_bfloat16* T4 = Tco + 4 * NE1 * HH;

    const int jbase = warp * 4 + g;

    int4 q0 = *(const int4*)&sidx[jbase * SST + 0];
    int4 q1 = *(const int4*)&sidx[jbase * SST + 4];
    int4 q2 = *(const int4*)&sidx[jbase * SST + 8];
    int4 q3 = *(const int4*)&sidx[jbase * SST + 12];
    int  spv = sspat[jbase];

#pragma unroll 1
    for (int k = 0; k < 4; ++k) {
        const int jh = k * 32 + jbase;

        // 15 independent LDG.64 gathers (d = t/3, t = 0..14), 4 bf16 ch each
        uint2 v0  = *(const uint2*)(T0 + q0.x * HH);
        uint2 v1  = *(const uint2*)(T0 + q0.y * HH);
        uint2 v2  = *(const uint2*)(T0 + q0.z * HH);
        uint2 v3  = *(const uint2*)(T1 + q0.w * HH);
        uint2 v4  = *(const uint2*)(T1 + q1.x * HH);
        uint2 v5  = *(const uint2*)(T1 + q1.y * HH);
        uint2 v6  = *(const uint2*)(T2 + q1.z * HH);
        uint2 v7  = *(const uint2*)(T2 + q1.w * HH);
        uint2 v8  = *(const uint2*)(T2 + q2.x * HH);
        uint2 v9  = *(const uint2*)(T3 + q2.y * HH);
        uint2 v10 = *(const uint2*)(T3 + q2.z * HH);
        uint2 v11 = *(const uint2*)(T3 + q2.w * HH);
        uint2 v12 = *(const uint2*)(T4 + q3.x * HH);
        uint2 v13 = *(const uint2*)(T4 + q3.y * HH);
        uint2 v14 = *(const uint2*)(T4 + q3.z * HH);
        const float4 sw = *(const float4*)(struct_w + spv * HH + co);

        // scale factor off the critical path (MUFU 16cyc)
        const int sp = (spv <= 1) ? 1 : min(spv - 1, DD);
        float s;
        asm("rcp.approx.f32 %0, %1;" : "=f"(s) : "f"(3.0f * (float)sp));

        // prefetch next iteration's indices while gathers are in flight
        if (k < 3) {
            const int jn = (k + 1) * 32 + jbase;
            q0  = *(const int4*)&sidx[jn * SST + 0];
            q1  = *(const int4*)&sidx[jn * SST + 4];
            q2  = *(const int4*)&sidx[jn * SST + 8];
            q3  = *(const int4*)&sidx[jn * SST + 12];
            spv = sspat[jn];
        }

        // depth-4 pairwise tree reduction in packed bf16x2
        U2_ADD(v0,  v1);  U2_ADD(v2,  v3);  U2_ADD(v4,  v5);
        U2_ADD(v6,  v7);  U2_ADD(v8,  v9);  U2_ADD(v10, v11);
        U2_ADD(v12, v13);
        U2_ADD(v0,  v2);  U2_ADD(v4,  v6);  U2_ADD(v8,  v10);
        U2_ADD(v12, v14);
        U2_ADD(v0,  v4);  U2_ADD(v8,  v12);
        U2_ADD(v0,  v8);

        // widen bf16x2 -> f32 (bf16 == high half of f32)
        const float f0 = __uint_as_float(v0.x << 16);
        const float f1 = __uint_as_float(v0.x & 0xffff0000u);
        const float f2 = __uint_as_float(v0.y << 16);
        const float f3 = __uint_as_float(v0.y & 0xffff0000u);

        float* rp = &row[jh * RST + co];
        rp[0] = fmaf(f0, s, sw.x);
        rp[1] = fmaf(f1, s, sw.y);
        rp[2] = fmaf(f2, s, sw.z);
        rp[3] = fmaf(f3, s, sw.w);
    }
    __syncthreads();

    // ---- phase 2: emit 32 x 129 slab; no div/mod, conflict-free LDS ----
    const int j1 = 1 + lane;
    const float a0 = ab_s[j1];
    const float a1 = ab_s[j1 + 32];
    const float a2 = ab_s[j1 + 64];
    const float a3 = ab_s[j1 + 96];
    const float az = ab_s[0];

#pragma unroll
    for (int hh = 0; hh < 4; ++hh) {
        const int h  = warp + hh * 8;
        const float vh = vs[h];
        float* ob = out + (((size_t)b * HH + h) * NP1 + io) * NP1;
        if (lane == 0) ob[0] = fmaf(2.f, az, vh);
        ob[j1]      = fmaf(2.f, a0, row[(lane)      * RST + h]);
        ob[j1 + 32] = fmaf(2.f, a1, row[(lane + 32) * RST + h]);
        ob[j1 + 64] = fmaf(2.f, a2, row[(lane + 64) * RST + h]);
        ob[j1 + 96] = fmaf(2.f, a3, row[(lane + 96) * RST + h]);
    }
}

// ---------------------------------------------------------------------------
extern "C" void kernel_launch(void* const* d_in, const int* in_sizes, int n_in,
                              void* d_out, int out_size)
{
    const float* ab    = (const float*)d_in[1];
    const int*   spat  = (const int*)  d_in[2];
    const int*   edge  = (const int*)  d_in[3];
    const float* ew    = (const float*)d_in[4];
    const float* sw    = (const float*)d_in[5];
    const float* wdis  = (const float*)d_in[6];
    const float* virt  = (const float*)d_in[7];
    float*       outp  = (float*)d_out;

    build_table_kernel<<<dim3((NE1 + 7) / 8, DD), dim3(32, 8)>>>(ew, wdis);
    bias_kernel<<<dim3(NP1, BB), 256>>>(ab, spat, edge, sw, virt, outp);
}